// round 7
// baseline (speedup 1.0000x reference)
#include <cuda_runtime.h>

// ---------------- problem constants ----------------
#define NXg 256
#define NYg 256
#define NG  (NXg*NYg)

// tile: interior 16(x) x 32(y), halo 4 -> ext 24x40; strips of 2 in y
#define IXt 16
#define IYt 32
#define Hh  4
#define EXt 24
#define EYt 40
#define EXT (EXt*EYt)      // 960
#define SW   2
#define NSTR (EYt/SW)      // 20
#define ACT  (EXt*NSTR)    // 480 active threads
#define NT   512
#define NBX (NYg/IYt)      // 8  y-tiles
#define NBY (NXg/IXt)      // 16 x-tiles
#define NCTA (NBX*NBY)     // 128 CTAs <= 148 SMs -> co-resident
#define RELAX  100
#define TSTEPS 1024

// ---------------- device state ----------------
__device__ float g_m[2][3*NG];       // ping-pong exchange state
__device__ unsigned g_flag[NCTA];    // per-CTA completed-step counter
__device__ unsigned g_count;
__device__ unsigned g_sense;         // 2 flips per run -> replay-safe

// init-only grid barrier (used twice per run: even sense flips)
__device__ __forceinline__ void gridbar(unsigned& lsense)
{
    __syncthreads();
    if (threadIdx.x == 0) {
        unsigned s = lsense ^ 1u;
        lsense = s;
        unsigned old;
        asm volatile("atom.add.acq_rel.gpu.u32 %0, [%1], 1;"
                     : "=r"(old) : "l"(&g_count) : "memory");
        if (old == NCTA - 1u) {
            asm volatile("st.relaxed.gpu.u32 [%0], %1;" :: "l"(&g_count), "r"(0u) : "memory");
            asm volatile("st.release.gpu.u32 [%0], %1;" :: "l"(&g_sense), "r"(s) : "memory");
        } else {
            unsigned v;
            do {
                asm volatile("ld.acquire.gpu.u32 %0, [%1];" : "=r"(v) : "l"(&g_sense) : "memory");
            } while (v != s);
        }
    }
    __syncthreads();
}

__global__ void __launch_bounds__(NT, 1)
k_sim(const float* __restrict__ sig,  const float* __restrict__ Bext,
      const float* __restrict__ Msat, const float* __restrict__ src,
      const float* __restrict__ pmask, float* __restrict__ out)
{
    __shared__ __align__(16) float SA[3][EXT];
    __shared__ __align__(16) float SB[3][EXT];
    __shared__ float red[NT/32];
    __shared__ float s_pminv;
    __shared__ float s_sig[TSTEPS];

    const int tid = threadIdx.x;
    const bool live = (tid < ACT);
    const int ex  = live ? tid / NSTR : 0;
    const int sy  = live ? tid % NSTR : 0;
    const int tx  = (int)blockIdx.y;          // x-tile 0..15
    const int ty  = (int)blockIdx.x;          // y-tile 0..7
    const int gx0 = tx * IXt - Hh;
    const int gy0 = ty * IYt - Hh;
    const int gx  = gx0 + ex;
    const int gyb = gy0 + SW*sy;
    const int e   = ex*EYt + SW*sy;

    const int gxc = min(max(gx, 0), NXg - 1);
    const int gyc = min(max(gyb, 0), NYg - SW);
    const int g   = gxc*NYg + gyc;

    const int exm = (ex == 0       || gx <= 0)       ? ex : ex - 1;
    const int exq = (ex == EXt - 1 || gx >= NXg - 1) ? ex : ex + 1;
    const int emb = exm*EYt + SW*sy;
    const int epb = exq*EYt + SW*sy;
    const int yL = (sy == 0        || gyb <= 0)                ? e          : e - 1;
    const int yR = (sy == NSTR - 1 || gyb + SW - 1 >= NYg - 1) ? e + SW - 1 : e + SW;

    const bool sint = live && ex >= Hh && ex < Hh + IXt && sy >= Hh/SW && sy < (Hh + IYt)/SW;
    const bool ring = sint && (ex < Hh + 4 || ex >= Hh + IXt - 4 ||
                               sy < Hh/SW + 2 || sy >= (Hh + IYt)/SW - 2);

    // ---- neighbor flag pointer for threads 0..7 (≤8 valid neighbors) ----
    const unsigned* nbp = nullptr;
    if (tid < 8) {
        // enumerate the 8 (dx,dy) offsets
        const int dxs[8] = {-1,-1,-1, 0, 0, 1, 1, 1};
        const int dys[8] = {-1, 0, 1,-1, 1,-1, 0, 1};
        int ntx = tx + dxs[tid], nty = ty + dys[tid];
        if (ntx >= 0 && ntx < NBY && nty >= 0 && nty < NBX)
            nbp = &g_flag[ntx * NBX + nty];
    }
    unsigned* const myflag = &g_flag[tx * NBX + ty];

    const float MU0f    = (float)(4e-7 * 3.14159265358979323846);
    const float TWO_A   = (float)(2.0 * 3.65e-12);
    const float INV_DX2 = (float)(1.0 / (50e-9 * 50e-9));
    const double hd  = 1.7595e11 * 5e-12;
    const float c05  = (float)(0.5 * hd);
    const float cfl  = (float)hd;
    const float h6   = (float)(hd / 6.0);
    const float a_rx = 0.5f,  i_rx = (float)(1.0 / (1.0 + 0.5 * 0.5));
    const float a_rn = 0.01f, i_rn = (float)(1.0 / (1.0 + 0.01 * 0.01));

    // -------- static per-cell constants (registers, whole run) --------
    float rB0[SW], rB1[SW], rB2[SW], rS0[SW], rS1[SW], rS2[SW];
    float rCL[SW], rDg[SW], pmw[SW], m0x[SW];
    int anyp = 0;
    #pragma unroll
    for (int j = 0; j < SW; j++) {
        int gyj = gyb + j;
        bool ok = live && gx >= 0 && gx < NXg && gyj >= 0 && gyj < NYg;
        int gj = ok ? gx*NYg + gyj : g;
        float ms = Msat[gj];
        rCL[j] = (TWO_A / ms) * INV_DX2;
        rDg[j] = MU0f * ms;
        rB0[j] = Bext[0*NG + gj]; rB1[j] = Bext[1*NG + gj]; rB2[j] = Bext[2*NG + gj];
        rS0[j] = src [0*NG + gj]; rS1[j] = src [1*NG + gj]; rS2[j] = src [2*NG + gj];
        float pv = (sint && ok) ? pmask[gj] : 0.f;
        pmw[j] = pv * ms;
        m0x[j] = 0.f;
        if (pv != 0.f) anyp = 1;
    }

    for (int i = tid; i < TSTEPS; i += NT) s_sig[i] = sig[i];
    if (blockIdx.x == 0 && blockIdx.y == 0)
        for (int i = tid; i < TSTEPS; i += NT) out[i] = 0.f;

    // reset own flag (before the init barriers)
    if (tid == 0)
        asm volatile("st.relaxed.gpu.u32 [%0], %1;" :: "l"(myflag), "r"(0u) : "memory");

    const int hasp = __syncthreads_or(anyp);
    if (hasp) {
        float s = 0.f;
        for (int i = tid; i < NG; i += NT) s += pmask[i];
        #pragma unroll
        for (int o = 16; o; o >>= 1) s += __shfl_down_sync(0xffffffffu, s, o);
        if ((tid & 31) == 0) red[tid >> 5] = s;
        __syncthreads();
        if (tid < 32) {
            float v = (tid < NT/32) ? red[tid] : 0.f;
            #pragma unroll
            for (int o = 8; o; o >>= 1) v += __shfl_down_sync(0xffffffffu, v, o);
            if (tid == 0) s_pminv = 1.f / v;
        }
    }

    // two grid barriers: all flags reset & out zeroed visible; even sense flips
    unsigned lsense = 0;
    gridbar(lsense);
    gridbar(lsense);

    // m carried in registers between steps; SA = step-start state
    float mb0[SW], mb1[SW], mb2[SW];
    #pragma unroll
    for (int j = 0; j < SW; j++) { mb0[j] = 0.f; mb1[j] = 0.f; mb2[j] = 1.f; }
    if (live) {
        *(float2*)&SA[0][e] = make_float2(0.f, 0.f);
        *(float2*)&SA[1][e] = make_float2(0.f, 0.f);
        *(float2*)&SA[2][e] = make_float2(1.f, 1.f);
    }
    __syncthreads();

    for (int step = 0; step < RELAX + TSTEPS; ++step) {
        const bool  probe = (step >= RELAX);
        const float sv    = probe ? s_sig[step - RELAX] : 0.f;
        const float alpha = probe ? a_rn : a_rx;
        const float inv1a = probe ? i_rn : i_rx;
        const float* __restrict__ m_in  = g_m[(step + 1) & 1];
        float*       __restrict__ m_out = g_m[step & 1];

        // ---- wait for the 8 neighbors to have completed step-1 ----
        if (step > 0 && tid < 8 && nbp) {
            unsigned v;
            do {
                asm volatile("ld.acquire.gpu.u32 %0, [%1];" : "=r"(v) : "l"(nbp) : "memory");
            } while (v < (unsigned)step);
        }

        float tB0[SW], tB1[SW], tB2[SW];
        float a0[SW], a1[SW], a2[SW];
        #pragma unroll
        for (int j = 0; j < SW; j++) {
            tB0[j] = fmaf(sv, rS0[j], rB0[j]);
            tB1[j] = fmaf(sv, rS1[j], rB1[j]);
            tB2[j] = fmaf(sv, rS2[j], rB2[j]);
            a0[j] = 0.f; a1[j] = 0.f; a2[j] = 0.f;
        }
        __syncthreads();   // flag-wait done before any halo read

        // ---- halo refresh from L2 ----
        if (live && !sint && step > 0) {
            float2 a = __ldcg((const float2*)&m_in[0*NG + g]);
            float2 b = __ldcg((const float2*)&m_in[1*NG + g]);
            float2 c = __ldcg((const float2*)&m_in[2*NG + g]);
            mb0[0]=a.x; mb0[1]=a.y;
            mb1[0]=b.x; mb1[1]=b.y;
            mb2[0]=c.x; mb2[1]=c.y;
            *(float2*)&SA[0][e] = a; *(float2*)&SA[1][e] = b; *(float2*)&SA[2][e] = c;
        }
        float st0[SW], st1[SW], st2[SW];
        #pragma unroll
        for (int j = 0; j < SW; j++) { st0[j] = mb0[j]; st1[j] = mb1[j]; st2[j] = mb2[j]; }
        __syncthreads();

        auto stage = [&](const float (*__restrict__ S)[EXT],
                         float (*__restrict__ D)[EXT],
                         float coef, float w, bool writeD) {
            float2 nm0 = *(const float2*)&S[0][emb];
            float2 nm1 = *(const float2*)&S[1][emb];
            float2 nm2 = *(const float2*)&S[2][emb];
            float2 np0 = *(const float2*)&S[0][epb];
            float2 np1 = *(const float2*)&S[1][epb];
            float2 np2 = *(const float2*)&S[2][epb];
            float lf0 = S[0][yL], lf1 = S[1][yL], lf2 = S[2][yL];
            float rg0 = S[0][yR], rg1 = S[1][yR], rg2 = S[2][yR];
            float xm0[SW] = {nm0.x, nm0.y}, xm1[SW] = {nm1.x, nm1.y}, xm2[SW] = {nm2.x, nm2.y};
            float xp0[SW] = {np0.x, np0.y}, xp1[SW] = {np1.x, np1.y}, xp2[SW] = {np2.x, np2.y};
            #pragma unroll
            for (int j = 0; j < SW; j++) {
                float mx = st0[j], my = st1[j], mz = st2[j];
                float yl0 = j ? st0[j-1] : lf0;
                float yl1 = j ? st1[j-1] : lf1;
                float yl2 = j ? st2[j-1] : lf2;
                float yr0 = (j < SW-1) ? st0[j+1] : rg0;
                float yr1 = (j < SW-1) ? st1[j+1] : rg1;
                float yr2 = (j < SW-1) ? st2[j+1] : rg2;
                float l0 = xm0[j] + xp0[j] + yl0 + yr0 - 4.f*mx;
                float l1 = xm1[j] + xp1[j] + yl1 + yr1 - 4.f*my;
                float l2 = xm2[j] + xp2[j] + yl2 + yr2 - 4.f*mz;
                float Bx = fmaf(rCL[j], l0, tB0[j]);
                float By = fmaf(rCL[j], l1, tB1[j]);
                float Bz = fmaf(rCL[j], l2, tB2[j]) - rDg[j]*mz;
                float px = my*Bz - mz*By;
                float py = mz*Bx - mx*Bz;
                float pz = mx*By - my*Bx;
                float qx = my*pz - mz*py;
                float qy = mz*px - mx*pz;
                float qz = mx*py - my*px;
                float k0 = -(px + alpha*qx) * inv1a;
                float k1 = -(py + alpha*qy) * inv1a;
                float k2 = -(pz + alpha*qz) * inv1a;
                a0[j] = fmaf(w, k0, a0[j]);
                a1[j] = fmaf(w, k1, a1[j]);
                a2[j] = fmaf(w, k2, a2[j]);
                st0[j] = fmaf(coef, k0, mb0[j]);
                st1[j] = fmaf(coef, k1, mb1[j]);
                st2[j] = fmaf(coef, k2, mb2[j]);
            }
            if (writeD && live) {
                *(float2*)&D[0][e] = make_float2(st0[0], st0[1]);
                *(float2*)&D[1][e] = make_float2(st1[0], st1[1]);
                *(float2*)&D[2][e] = make_float2(st2[0], st2[1]);
            }
        };

        stage(SA, SB, c05, 1.f, true); __syncthreads();
        stage(SB, SA, c05, 2.f, true); __syncthreads();
        stage(SA, SB, cfl, 2.f, true); __syncthreads();
        stage(SB, SA, 0.f, 1.f, false);   // k4 folded into acc

        // ---- final m (interior): SA publish + exchange ring to L2 ----
        float part = 0.f;
        if (sint) {
            #pragma unroll
            for (int j = 0; j < SW; j++) {
                mb0[j] = fmaf(h6, a0[j], mb0[j]);
                mb1[j] = fmaf(h6, a1[j], mb1[j]);
                mb2[j] = fmaf(h6, a2[j], mb2[j]);
                if (step == RELAX - 1) m0x[j] = mb0[j];
                if (probe) part += (mb0[j] - m0x[j]) * pmw[j];
            }
            float2 a = make_float2(mb0[0], mb0[1]);
            float2 b = make_float2(mb1[0], mb1[1]);
            float2 c = make_float2(mb2[0], mb2[1]);
            *(float2*)&SA[0][e] = a; *(float2*)&SA[1][e] = b; *(float2*)&SA[2][e] = c;
            if (ring) {
                __stcg((float2*)&m_out[0*NG + g], a);
                __stcg((float2*)&m_out[1*NG + g], b);
                __stcg((float2*)&m_out[2*NG + g], c);
            }
        }

        // ---- publish completion of this step (after all ring stores) ----
        __syncthreads();
        if (tid == 0)
            asm volatile("st.release.gpu.u32 [%0], %1;"
                         :: "l"(myflag), "r"((unsigned)(step + 1)) : "memory");

        if (probe && hasp) {
            #pragma unroll
            for (int o = 16; o; o >>= 1) part += __shfl_down_sync(0xffffffffu, part, o);
            if ((tid & 31) == 0) red[tid >> 5] = part;
            __syncthreads();
            if (tid < 32) {
                float v2 = (tid < NT/32) ? red[tid] : 0.f;
                #pragma unroll
                for (int o = 8; o; o >>= 1) v2 += __shfl_down_sync(0xffffffffu, v2, o);
                if (tid == 0) atomicAdd(&out[step - RELAX], v2 * s_pminv);
            }
            __syncthreads();   // red[] reuse safety across steps
        }
    }
}

// ---------------- host launcher: ONE graph node ----------------
extern "C" void kernel_launch(void* const* d_in, const int* in_sizes, int n_in,
                              void* d_out, int out_size)
{
    const float* sig   = (const float*)d_in[0];
    const float* Bext  = (const float*)d_in[1];
    const float* Msat  = (const float*)d_in[2];
    const float* src   = (const float*)d_in[3];
    const float* pmask = (const float*)d_in[4];
    float* out = (float*)d_out;

    dim3 grid(NBX, NBY);
    k_sim<<<grid, NT>>>(sig, Bext, Msat, src, pmask, out);
}

// round 8
// speedup vs baseline: 1.1903x; 1.1903x over previous
#include <cuda_runtime.h>

// ---------------- problem constants ----------------
#define NXg 256
#define NYg 256
#define NG  (NXg*NYg)

// tile: interior 16(x) x 32(y), halo 4 -> ext 24x40; strips of 2 in y
#define IXt 16
#define IYt 32
#define Hh  4
#define EXt 24
#define EYt 40
#define EXT (EXt*EYt)      // 960
#define SW   2
#define NSTR (EYt/SW)      // 20
#define ACT  (EXt*NSTR)    // 480 active threads
#define NT   512
#define NBX (NYg/IYt)      // 8
#define NBY (NXg/IXt)      // 16
#define NCTA (NBX*NBY)     // 128 CTAs <= 148 SMs -> co-resident
#define RELAX  100
#define TSTEPS 1024
#define NSTEPS (RELAX + TSTEPS)

// ---------------- device state ----------------
__device__ float g_m[2][3*NG];   // ping-pong exchange state
__device__ unsigned g_count;     // MONOTONIC arrival counter (reset at kernel start)
__device__ unsigned g_sense;     // last released step (reset at kernel start)
__device__ unsigned g_ibar;      // init barrier counter (self-resetting)
__device__ unsigned g_isense;    // init barrier sense (2 flips/run -> replay-safe)

// init-only sense-reversing barrier (used exactly twice per run)
__device__ __forceinline__ void initbar(unsigned& lsense)
{
    __syncthreads();
    if (threadIdx.x == 0) {
        unsigned s = lsense ^ 1u;
        lsense = s;
        unsigned old;
        asm volatile("atom.add.acq_rel.gpu.u32 %0, [%1], 1;"
                     : "=r"(old) : "l"(&g_ibar) : "memory");
        if (old == NCTA - 1u) {
            asm volatile("st.relaxed.gpu.u32 [%0], %1;" :: "l"(&g_ibar), "r"(0u) : "memory");
            asm volatile("st.release.gpu.u32 [%0], %1;" :: "l"(&g_isense), "r"(s) : "memory");
        } else {
            unsigned v;
            do {
                asm volatile("ld.acquire.gpu.u32 %0, [%1];" : "=r"(v) : "l"(&g_isense) : "memory");
            } while (v != s);
        }
    }
    __syncthreads();
}

__global__ void __launch_bounds__(NT, 1)
k_sim(const float* __restrict__ sig,  const float* __restrict__ Bext,
      const float* __restrict__ Msat, const float* __restrict__ src,
      const float* __restrict__ pmask, float* __restrict__ out)
{
    __shared__ __align__(16) float SA[3][EXT];
    __shared__ __align__(16) float SB[3][EXT];
    __shared__ float red[NT/32];
    __shared__ float s_pminv;
    __shared__ float s_sig[TSTEPS];

    const int tid = threadIdx.x;
    const bool live = (tid < ACT);
    const int ex  = live ? tid / NSTR : 0;
    const int sy  = live ? tid % NSTR : 0;
    const int gx0 = (int)blockIdx.y * IXt - Hh;
    const int gy0 = (int)blockIdx.x * IYt - Hh;
    const int gx  = gx0 + ex;
    const int gyb = gy0 + SW*sy;
    const int e   = ex*EYt + SW*sy;
    const bool cta0 = (blockIdx.x == 0 && blockIdx.y == 0);

    const int gxc = min(max(gx, 0), NXg - 1);
    const int gyc = min(max(gyb, 0), NYg - SW);
    const int g   = gxc*NYg + gyc;

    const int exm = (ex == 0       || gx <= 0)       ? ex : ex - 1;
    const int exq = (ex == EXt - 1 || gx >= NXg - 1) ? ex : ex + 1;
    const int emb = exm*EYt + SW*sy;
    const int epb = exq*EYt + SW*sy;
    const int yL = (sy == 0        || gyb <= 0)                ? e          : e - 1;
    const int yR = (sy == NSTR - 1 || gyb + SW - 1 >= NYg - 1) ? e + SW - 1 : e + SW;

    const bool sint = live && ex >= Hh && ex < Hh + IXt && sy >= Hh/SW && sy < (Hh + IYt)/SW;
    const bool ring = sint && (ex < Hh + 4 || ex >= Hh + IXt - 4 ||
                               sy < Hh/SW + 2 || sy >= (Hh + IYt)/SW - 2);

    const float MU0f    = (float)(4e-7 * 3.14159265358979323846);
    const float TWO_A   = (float)(2.0 * 3.65e-12);
    const float INV_DX2 = (float)(1.0 / (50e-9 * 50e-9));
    const double hd  = 1.7595e11 * 5e-12;
    const float c05  = (float)(0.5 * hd);
    const float cfl  = (float)hd;
    const float h6   = (float)(hd / 6.0);
    const float a_rx = 0.5f,  i_rx = (float)(1.0 / (1.0 + 0.5 * 0.5));
    const float a_rn = 0.01f, i_rn = (float)(1.0 / (1.0 + 0.01 * 0.01));

    // -------- static per-cell constants (registers, whole run) --------
    float rB0[SW], rB1[SW], rB2[SW], rS0[SW], rS1[SW], rS2[SW];
    float rCL[SW], rDg[SW], pmw[SW], m0x[SW];
    int anyp = 0;
    #pragma unroll
    for (int j = 0; j < SW; j++) {
        int gyj = gyb + j;
        bool ok = live && gx >= 0 && gx < NXg && gyj >= 0 && gyj < NYg;
        int gj = ok ? gx*NYg + gyj : g;
        float ms = Msat[gj];
        rCL[j] = (TWO_A / ms) * INV_DX2;
        rDg[j] = MU0f * ms;
        rB0[j] = Bext[0*NG + gj]; rB1[j] = Bext[1*NG + gj]; rB2[j] = Bext[2*NG + gj];
        rS0[j] = src [0*NG + gj]; rS1[j] = src [1*NG + gj]; rS2[j] = src [2*NG + gj];
        float pv = (sint && ok) ? pmask[gj] : 0.f;
        pmw[j] = pv * ms;
        m0x[j] = 0.f;
        if (pv != 0.f) anyp = 1;
    }

    for (int i = tid; i < TSTEPS; i += NT) s_sig[i] = sig[i];
    if (cta0) {
        for (int i = tid; i < TSTEPS; i += NT) out[i] = 0.f;
        if (tid == 0) {   // replay reset, published by the init barriers below
            asm volatile("st.relaxed.gpu.u32 [%0], %1;" :: "l"(&g_count), "r"(0u) : "memory");
            asm volatile("st.relaxed.gpu.u32 [%0], %1;" :: "l"(&g_sense), "r"(0u) : "memory");
        }
    }

    const int hasp = __syncthreads_or(anyp);
    if (hasp) {
        float s = 0.f;
        for (int i = tid; i < NG; i += NT) s += pmask[i];
        #pragma unroll
        for (int o = 16; o; o >>= 1) s += __shfl_down_sync(0xffffffffu, s, o);
        if ((tid & 31) == 0) red[tid >> 5] = s;
        __syncthreads();
        if (tid < 32) {
            float v = (tid < NT/32) ? red[tid] : 0.f;
            #pragma unroll
            for (int o = 8; o; o >>= 1) v += __shfl_down_sync(0xffffffffu, v, o);
            if (tid == 0) s_pminv = 1.f / v;
        }
    }

    // two init barriers: resets visible everywhere; g_isense flips evenly
    unsigned lsense = 0;
    initbar(lsense);
    initbar(lsense);

    // m carried in registers between steps; SA = step-start state
    float mb0[SW], mb1[SW], mb2[SW];
    #pragma unroll
    for (int j = 0; j < SW; j++) { mb0[j] = 0.f; mb1[j] = 0.f; mb2[j] = 1.f; }
    if (live) {
        *(float2*)&SA[0][e] = make_float2(0.f, 0.f);
        *(float2*)&SA[1][e] = make_float2(0.f, 0.f);
        *(float2*)&SA[2][e] = make_float2(1.f, 1.f);
    }
    __syncthreads();

    for (int step = 0; step < NSTEPS; ++step) {
        const bool  probe = (step >= RELAX);
        const float sv    = probe ? s_sig[step - RELAX] : 0.f;
        const float alpha = probe ? a_rn : a_rx;
        const float inv1a = probe ? i_rn : i_rx;
        const float* __restrict__ m_in  = g_m[(step + 1) & 1];
        float*       __restrict__ m_out = g_m[step & 1];

        // ---- halo refresh from L2, issued first after the barrier ----
        if (live && !sint && step > 0) {
            float2 a = __ldcg((const float2*)&m_in[0*NG + g]);
            float2 b = __ldcg((const float2*)&m_in[1*NG + g]);
            float2 c = __ldcg((const float2*)&m_in[2*NG + g]);
            mb0[0]=a.x; mb0[1]=a.y;
            mb1[0]=b.x; mb1[1]=b.y;
            mb2[0]=c.x; mb2[1]=c.y;
            *(float2*)&SA[0][e] = a; *(float2*)&SA[1][e] = b; *(float2*)&SA[2][e] = c;
        }

        float tB0[SW], tB1[SW], tB2[SW];
        float st0[SW], st1[SW], st2[SW];
        float a0[SW], a1[SW], a2[SW];
        #pragma unroll
        for (int j = 0; j < SW; j++) {
            tB0[j] = fmaf(sv, rS0[j], rB0[j]);
            tB1[j] = fmaf(sv, rS1[j], rB1[j]);
            tB2[j] = fmaf(sv, rS2[j], rB2[j]);
            st0[j] = mb0[j]; st1[j] = mb1[j]; st2[j] = mb2[j];
            a0[j] = 0.f; a1[j] = 0.f; a2[j] = 0.f;
        }
        __syncthreads();

        auto stage = [&](const float (*__restrict__ S)[EXT],
                         float (*__restrict__ D)[EXT],
                         float coef, float w, bool writeD) {
            float2 nm0 = *(const float2*)&S[0][emb];
            float2 nm1 = *(const float2*)&S[1][emb];
            float2 nm2 = *(const float2*)&S[2][emb];
            float2 np0 = *(const float2*)&S[0][epb];
            float2 np1 = *(const float2*)&S[1][epb];
            float2 np2 = *(const float2*)&S[2][epb];
            float lf0 = S[0][yL], lf1 = S[1][yL], lf2 = S[2][yL];
            float rg0 = S[0][yR], rg1 = S[1][yR], rg2 = S[2][yR];
            float xm0[SW] = {nm0.x, nm0.y}, xm1[SW] = {nm1.x, nm1.y}, xm2[SW] = {nm2.x, nm2.y};
            float xp0[SW] = {np0.x, np0.y}, xp1[SW] = {np1.x, np1.y}, xp2[SW] = {np2.x, np2.y};
            #pragma unroll
            for (int j = 0; j < SW; j++) {
                float mx = st0[j], my = st1[j], mz = st2[j];
                float yl0 = j ? st0[j-1] : lf0;
                float yl1 = j ? st1[j-1] : lf1;
                float yl2 = j ? st2[j-1] : lf2;
                float yr0 = (j < SW-1) ? st0[j+1] : rg0;
                float yr1 = (j < SW-1) ? st1[j+1] : rg1;
                float yr2 = (j < SW-1) ? st2[j+1] : rg2;
                float l0 = xm0[j] + xp0[j] + yl0 + yr0 - 4.f*mx;
                float l1 = xm1[j] + xp1[j] + yl1 + yr1 - 4.f*my;
                float l2 = xm2[j] + xp2[j] + yl2 + yr2 - 4.f*mz;
                float Bx = fmaf(rCL[j], l0, tB0[j]);
                float By = fmaf(rCL[j], l1, tB1[j]);
                float Bz = fmaf(rCL[j], l2, tB2[j]) - rDg[j]*mz;
                float px = my*Bz - mz*By;
                float py = mz*Bx - mx*Bz;
                float pz = mx*By - my*Bx;
                float qx = my*pz - mz*py;
                float qy = mz*px - mx*pz;
                float qz = mx*py - my*px;
                float k0 = -(px + alpha*qx) * inv1a;
                float k1 = -(py + alpha*qy) * inv1a;
                float k2 = -(pz + alpha*qz) * inv1a;
                a0[j] = fmaf(w, k0, a0[j]);
                a1[j] = fmaf(w, k1, a1[j]);
                a2[j] = fmaf(w, k2, a2[j]);
                st0[j] = fmaf(coef, k0, mb0[j]);
                st1[j] = fmaf(coef, k1, mb1[j]);
                st2[j] = fmaf(coef, k2, mb2[j]);
            }
            if (writeD && live) {
                *(float2*)&D[0][e] = make_float2(st0[0], st0[1]);
                *(float2*)&D[1][e] = make_float2(st1[0], st1[1]);
                *(float2*)&D[2][e] = make_float2(st2[0], st2[1]);
            }
        };

        stage(SA, SB, c05, 1.f, true); __syncthreads();
        stage(SB, SA, c05, 2.f, true); __syncthreads();
        stage(SA, SB, cfl, 2.f, true); __syncthreads();
        stage(SB, SA, 0.f, 1.f, false);   // k4 folded into acc

        // ---- final m (interior): SA publish + exchange ring to L2 ----
        float part = 0.f;
        if (sint) {
            #pragma unroll
            for (int j = 0; j < SW; j++) {
                mb0[j] = fmaf(h6, a0[j], mb0[j]);
                mb1[j] = fmaf(h6, a1[j], mb1[j]);
                mb2[j] = fmaf(h6, a2[j], mb2[j]);
                if (step == RELAX - 1) m0x[j] = mb0[j];
                if (probe) part += (mb0[j] - m0x[j]) * pmw[j];
            }
            float2 a = make_float2(mb0[0], mb0[1]);
            float2 b = make_float2(mb1[0], mb1[1]);
            float2 c = make_float2(mb2[0], mb2[1]);
            *(float2*)&SA[0][e] = a; *(float2*)&SA[1][e] = b; *(float2*)&SA[2][e] = c;
            if (ring) {
                __stcg((float2*)&m_out[0*NG + g], a);
                __stcg((float2*)&m_out[1*NG + g], b);
                __stcg((float2*)&m_out[2*NG + g], c);
            }
        }

        if (step == NSTEPS - 1) {
            // last step: no barrier needed; just finish probe and exit
            if (probe && hasp) {
                #pragma unroll
                for (int o = 16; o; o >>= 1) part += __shfl_down_sync(0xffffffffu, part, o);
                if ((tid & 31) == 0) red[tid >> 5] = part;
                __syncthreads();
                if (tid < 32) {
                    float v2 = (tid < NT/32) ? red[tid] : 0.f;
                    #pragma unroll
                    for (int o = 8; o; o >>= 1) v2 += __shfl_down_sync(0xffffffffu, v2, o);
                    if (tid == 0) atomicAdd(&out[step - RELAX], v2 * s_pminv);
                }
            }
            break;
        }

        // ---- arrive: fire-and-forget, orders prior ring stores ----
        __syncthreads();
        if (tid == 0)
            asm volatile("red.add.release.gpu.u32 [%0], %1;"
                         :: "l"(&g_count), "r"(1u) : "memory");

        // ---- probe reduction overlaps other CTAs' spin ----
        if (probe && hasp) {
            #pragma unroll
            for (int o = 16; o; o >>= 1) part += __shfl_down_sync(0xffffffffu, part, o);
            if ((tid & 31) == 0) red[tid >> 5] = part;
            __syncthreads();
            if (tid < 32) {
                float v2 = (tid < NT/32) ? red[tid] : 0.f;
                #pragma unroll
                for (int o = 8; o; o >>= 1) v2 += __shfl_down_sync(0xffffffffu, v2, o);
                if (tid == 0) atomicAdd(&out[step - RELAX], v2 * s_pminv);
            }
        }

        // ---- wait: CTA0 polls monotonic count, publishes sense ----
        if (tid == 0) {
            const unsigned tgt = (unsigned)(step + 1);
            unsigned v;
            if (cta0) {
                const unsigned need = tgt * (unsigned)NCTA;
                do {
                    asm volatile("ld.acquire.gpu.u32 %0, [%1];" : "=r"(v) : "l"(&g_count) : "memory");
                } while (v < need);
                asm volatile("st.release.gpu.u32 [%0], %1;" :: "l"(&g_sense), "r"(tgt) : "memory");
            } else {
                do {
                    asm volatile("ld.acquire.gpu.u32 %0, [%1];" : "=r"(v) : "l"(&g_sense) : "memory");
                } while (v < tgt);
            }
        }
        __syncthreads();
    }
}

// ---------------- host launcher: ONE graph node ----------------
extern "C" void kernel_launch(void* const* d_in, const int* in_sizes, int n_in,
                              void* d_out, int out_size)
{
    const float* sig   = (const float*)d_in[0];
    const float* Bext  = (const float*)d_in[1];
    const float* Msat  = (const float*)d_in[2];
    const float* src   = (const float*)d_in[3];
    const float* pmask = (const float*)d_in[4];
    float* out = (float*)d_out;

    dim3 grid(NBX, NBY);
    k_sim<<<grid, NT>>>(sig, Bext, Msat, src, pmask, out);
}

// round 9
// speedup vs baseline: 1.4647x; 1.2306x over previous
#include <cuda_runtime.h>

// ---------------- problem constants ----------------
#define NXg 256
#define NYg 256
#define NG  (NXg*NYg)

// tile: interior 16(x) x 32(y), halo 4 -> ext 24x40; strips of 2 in y
#define IXt 16
#define IYt 32
#define Hh  4
#define EXt 24
#define EYt 40
#define EXT (EXt*EYt)      // 960
#define SW   2
#define NSTR (EYt/SW)      // 20
#define ACT  (EXt*NSTR)    // 480 active threads
#define NT   512
#define NBX (NYg/IYt)      // 8
#define NBY (NXg/IXt)      // 16
#define NCTA (NBX*NBY)     // 128 CTAs <= 148 SMs -> co-resident
#define RELAX  100
#define TSTEPS 1024
#define NSTEPS (RELAX + TSTEPS)

// ---------------- device state ----------------
__device__ float g_m[2][3*NG];   // ping-pong exchange state
__device__ unsigned g_count;     // MONOTONIC arrival counter (reset at kernel start)
__device__ unsigned g_ibar;      // init barrier counter (self-resetting)
__device__ unsigned g_isense;    // init barrier sense (2 flips/run -> replay-safe)

// init-only sense-reversing barrier (used exactly twice per run)
__device__ __forceinline__ void initbar(unsigned& lsense)
{
    __syncthreads();
    if (threadIdx.x == 0) {
        unsigned s = lsense ^ 1u;
        lsense = s;
        unsigned old;
        asm volatile("atom.add.acq_rel.gpu.u32 %0, [%1], 1;"
                     : "=r"(old) : "l"(&g_ibar) : "memory");
        if (old == NCTA - 1u) {
            asm volatile("st.relaxed.gpu.u32 [%0], %1;" :: "l"(&g_ibar), "r"(0u) : "memory");
            asm volatile("st.release.gpu.u32 [%0], %1;" :: "l"(&g_isense), "r"(s) : "memory");
        } else {
            unsigned v;
            do {
                asm volatile("ld.acquire.gpu.u32 %0, [%1];" : "=r"(v) : "l"(&g_isense) : "memory");
            } while (v != s);
        }
    }
    __syncthreads();
}

__global__ void __launch_bounds__(NT, 1)
k_sim(const float* __restrict__ sig,  const float* __restrict__ Bext,
      const float* __restrict__ Msat, const float* __restrict__ src,
      const float* __restrict__ pmask, float* __restrict__ out)
{
    __shared__ __align__(16) float SA[3][EXT];
    __shared__ __align__(16) float SB[3][EXT];
    __shared__ float red[NT/32];
    __shared__ float s_pminv;
    __shared__ float s_sig[TSTEPS];

    const int tid = threadIdx.x;
    const bool live = (tid < ACT);
    const int ex  = live ? tid / NSTR : 0;
    const int sy  = live ? tid % NSTR : 0;
    const int gx0 = (int)blockIdx.y * IXt - Hh;
    const int gy0 = (int)blockIdx.x * IYt - Hh;
    const int gx  = gx0 + ex;
    const int gyb = gy0 + SW*sy;
    const int e   = ex*EYt + SW*sy;
    const bool cta0 = (blockIdx.x == 0 && blockIdx.y == 0);

    const int gxc = min(max(gx, 0), NXg - 1);
    const int gyc = min(max(gyb, 0), NYg - SW);
    const int g   = gxc*NYg + gyc;

    const int exm = (ex == 0       || gx <= 0)       ? ex : ex - 1;
    const int exq = (ex == EXt - 1 || gx >= NXg - 1) ? ex : ex + 1;
    const int emb = exm*EYt + SW*sy;
    const int epb = exq*EYt + SW*sy;
    const int yL = (sy == 0        || gyb <= 0)                ? e          : e - 1;
    const int yR = (sy == NSTR - 1 || gyb + SW - 1 >= NYg - 1) ? e + SW - 1 : e + SW;

    const bool sint = live && ex >= Hh && ex < Hh + IXt && sy >= Hh/SW && sy < (Hh + IYt)/SW;
    const bool ring = sint && (ex < Hh + 4 || ex >= Hh + IXt - 4 ||
                               sy < Hh/SW + 2 || sy >= (Hh + IYt)/SW - 2);

    const float MU0f    = (float)(4e-7 * 3.14159265358979323846);
    const float TWO_A   = (float)(2.0 * 3.65e-12);
    const float INV_DX2 = (float)(1.0 / (50e-9 * 50e-9));
    const double hd  = 1.7595e11 * 5e-12;
    const float c05  = (float)(0.5 * hd);
    const float cfl  = (float)hd;
    const float h6   = (float)(hd / 6.0);
    const float a_rx = 0.5f,  i_rx = (float)(1.0 / (1.0 + 0.5 * 0.5));
    const float a_rn = 0.01f, i_rn = (float)(1.0 / (1.0 + 0.01 * 0.01));

    // -------- static per-cell constants (registers, whole run) --------
    float rB0[SW], rB1[SW], rB2[SW], rS0[SW], rS1[SW], rS2[SW];
    float rCL[SW], rDg[SW], pmw[SW], m0x[SW];
    int anyp = 0;
    #pragma unroll
    for (int j = 0; j < SW; j++) {
        int gyj = gyb + j;
        bool ok = live && gx >= 0 && gx < NXg && gyj >= 0 && gyj < NYg;
        int gj = ok ? gx*NYg + gyj : g;
        float ms = Msat[gj];
        rCL[j] = (TWO_A / ms) * INV_DX2;
        rDg[j] = MU0f * ms;
        rB0[j] = Bext[0*NG + gj]; rB1[j] = Bext[1*NG + gj]; rB2[j] = Bext[2*NG + gj];
        rS0[j] = src [0*NG + gj]; rS1[j] = src [1*NG + gj]; rS2[j] = src [2*NG + gj];
        float pv = (sint && ok) ? pmask[gj] : 0.f;
        pmw[j] = pv * ms;
        m0x[j] = 0.f;
        if (pv != 0.f) anyp = 1;
    }

    for (int i = tid; i < TSTEPS; i += NT) s_sig[i] = sig[i];
    if (cta0) {
        for (int i = tid; i < TSTEPS; i += NT) out[i] = 0.f;
        if (tid == 0)   // replay reset, published by the init barriers below
            asm volatile("st.relaxed.gpu.u32 [%0], %1;" :: "l"(&g_count), "r"(0u) : "memory");
    }

    const int hasp = __syncthreads_or(anyp);
    if (hasp) {
        float s = 0.f;
        for (int i = tid; i < NG; i += NT) s += pmask[i];
        #pragma unroll
        for (int o = 16; o; o >>= 1) s += __shfl_down_sync(0xffffffffu, s, o);
        if ((tid & 31) == 0) red[tid >> 5] = s;
        __syncthreads();
        if (tid < 32) {
            float v = (tid < NT/32) ? red[tid] : 0.f;
            #pragma unroll
            for (int o = 8; o; o >>= 1) v += __shfl_down_sync(0xffffffffu, v, o);
            if (tid == 0) s_pminv = 1.f / v;
        }
    }

    // two init barriers: reset visible everywhere; g_isense flips evenly
    unsigned lsense = 0;
    initbar(lsense);
    initbar(lsense);

    // m carried in registers between steps; SA = step-start state
    float mb0[SW], mb1[SW], mb2[SW];
    #pragma unroll
    for (int j = 0; j < SW; j++) { mb0[j] = 0.f; mb1[j] = 0.f; mb2[j] = 1.f; }
    if (live) {
        *(float2*)&SA[0][e] = make_float2(0.f, 0.f);
        *(float2*)&SA[1][e] = make_float2(0.f, 0.f);
        *(float2*)&SA[2][e] = make_float2(1.f, 1.f);
    }
    __syncthreads();

    for (int step = 0; step < NSTEPS; ++step) {
        const bool  probe = (step >= RELAX);
        const float sv    = probe ? s_sig[step - RELAX] : 0.f;
        const float alpha = probe ? a_rn : a_rx;
        const float inv1a = probe ? i_rn : i_rx;
        const float* __restrict__ m_in  = g_m[(step + 1) & 1];
        float*       __restrict__ m_out = g_m[step & 1];

        // ---- halo refresh from L2, issued first after the barrier ----
        if (live && !sint && step > 0) {
            float2 a = __ldcg((const float2*)&m_in[0*NG + g]);
            float2 b = __ldcg((const float2*)&m_in[1*NG + g]);
            float2 c = __ldcg((const float2*)&m_in[2*NG + g]);
            mb0[0]=a.x; mb0[1]=a.y;
            mb1[0]=b.x; mb1[1]=b.y;
            mb2[0]=c.x; mb2[1]=c.y;
            *(float2*)&SA[0][e] = a; *(float2*)&SA[1][e] = b; *(float2*)&SA[2][e] = c;
        }

        float tB0[SW], tB1[SW], tB2[SW];
        float st0[SW], st1[SW], st2[SW];
        float a0[SW], a1[SW], a2[SW];
        #pragma unroll
        for (int j = 0; j < SW; j++) {
            tB0[j] = fmaf(sv, rS0[j], rB0[j]);
            tB1[j] = fmaf(sv, rS1[j], rB1[j]);
            tB2[j] = fmaf(sv, rS2[j], rB2[j]);
            st0[j] = mb0[j]; st1[j] = mb1[j]; st2[j] = mb2[j];
            a0[j] = 0.f; a1[j] = 0.f; a2[j] = 0.f;
        }
        __syncthreads();

        auto stage = [&](const float (*__restrict__ S)[EXT],
                         float (*__restrict__ D)[EXT],
                         float coef, float w, bool writeD) {
            float2 nm0 = *(const float2*)&S[0][emb];
            float2 nm1 = *(const float2*)&S[1][emb];
            float2 nm2 = *(const float2*)&S[2][emb];
            float2 np0 = *(const float2*)&S[0][epb];
            float2 np1 = *(const float2*)&S[1][epb];
            float2 np2 = *(const float2*)&S[2][epb];
            float lf0 = S[0][yL], lf1 = S[1][yL], lf2 = S[2][yL];
            float rg0 = S[0][yR], rg1 = S[1][yR], rg2 = S[2][yR];
            float xm0[SW] = {nm0.x, nm0.y}, xm1[SW] = {nm1.x, nm1.y}, xm2[SW] = {nm2.x, nm2.y};
            float xp0[SW] = {np0.x, np0.y}, xp1[SW] = {np1.x, np1.y}, xp2[SW] = {np2.x, np2.y};
            #pragma unroll
            for (int j = 0; j < SW; j++) {
                float mx = st0[j], my = st1[j], mz = st2[j];
                float yl0 = j ? st0[j-1] : lf0;
                float yl1 = j ? st1[j-1] : lf1;
                float yl2 = j ? st2[j-1] : lf2;
                float yr0 = (j < SW-1) ? st0[j+1] : rg0;
                float yr1 = (j < SW-1) ? st1[j+1] : rg1;
                float yr2 = (j < SW-1) ? st2[j+1] : rg2;
                float l0 = xm0[j] + xp0[j] + yl0 + yr0 - 4.f*mx;
                float l1 = xm1[j] + xp1[j] + yl1 + yr1 - 4.f*my;
                float l2 = xm2[j] + xp2[j] + yl2 + yr2 - 4.f*mz;
                float Bx = fmaf(rCL[j], l0, tB0[j]);
                float By = fmaf(rCL[j], l1, tB1[j]);
                float Bz = fmaf(rCL[j], l2, tB2[j]) - rDg[j]*mz;
                float px = my*Bz - mz*By;
                float py = mz*Bx - mx*Bz;
                float pz = mx*By - my*Bx;
                float qx = my*pz - mz*py;
                float qy = mz*px - mx*pz;
                float qz = mx*py - my*px;
                float k0 = -(px + alpha*qx) * inv1a;
                float k1 = -(py + alpha*qy) * inv1a;
                float k2 = -(pz + alpha*qz) * inv1a;
                a0[j] = fmaf(w, k0, a0[j]);
                a1[j] = fmaf(w, k1, a1[j]);
                a2[j] = fmaf(w, k2, a2[j]);
                st0[j] = fmaf(coef, k0, mb0[j]);
                st1[j] = fmaf(coef, k1, mb1[j]);
                st2[j] = fmaf(coef, k2, mb2[j]);
            }
            if (writeD && live) {
                *(float2*)&D[0][e] = make_float2(st0[0], st0[1]);
                *(float2*)&D[1][e] = make_float2(st1[0], st1[1]);
                *(float2*)&D[2][e] = make_float2(st2[0], st2[1]);
            }
        };

        stage(SA, SB, c05, 1.f, true); __syncthreads();
        stage(SB, SA, c05, 2.f, true); __syncthreads();
        stage(SA, SB, cfl, 2.f, true); __syncthreads();
        stage(SB, SA, 0.f, 1.f, false);   // k4 folded into acc

        // ---- final m (interior): SA publish + exchange ring to L2 ----
        float part = 0.f;
        if (sint) {
            #pragma unroll
            for (int j = 0; j < SW; j++) {
                mb0[j] = fmaf(h6, a0[j], mb0[j]);
                mb1[j] = fmaf(h6, a1[j], mb1[j]);
                mb2[j] = fmaf(h6, a2[j], mb2[j]);
                if (step == RELAX - 1) m0x[j] = mb0[j];
                if (probe) part += (mb0[j] - m0x[j]) * pmw[j];
            }
            float2 a = make_float2(mb0[0], mb0[1]);
            float2 b = make_float2(mb1[0], mb1[1]);
            float2 c = make_float2(mb2[0], mb2[1]);
            *(float2*)&SA[0][e] = a; *(float2*)&SA[1][e] = b; *(float2*)&SA[2][e] = c;
            if (ring) {
                __stcg((float2*)&m_out[0*NG + g], a);
                __stcg((float2*)&m_out[1*NG + g], b);
                __stcg((float2*)&m_out[2*NG + g], c);
            }
        }

        if (step == NSTEPS - 1) {
            if (probe && hasp) {
                #pragma unroll
                for (int o = 16; o; o >>= 1) part += __shfl_down_sync(0xffffffffu, part, o);
                if ((tid & 31) == 0) red[tid >> 5] = part;
                __syncthreads();
                if (tid < 32) {
                    float v2 = (tid < NT/32) ? red[tid] : 0.f;
                    #pragma unroll
                    for (int o = 8; o; o >>= 1) v2 += __shfl_down_sync(0xffffffffu, v2, o);
                    if (tid == 0) atomicAdd(&out[step - RELAX], v2 * s_pminv);
                }
            }
            break;
        }

        // ---- arrive: fire-and-forget, orders prior ring stores ----
        __syncthreads();
        if (tid == 0)
            asm volatile("red.add.release.gpu.u32 [%0], %1;"
                         :: "l"(&g_count), "r"(1u) : "memory");

        // ---- probe reduction overlaps other CTAs' spin ----
        if (probe && hasp) {
            #pragma unroll
            for (int o = 16; o; o >>= 1) part += __shfl_down_sync(0xffffffffu, part, o);
            if ((tid & 31) == 0) red[tid >> 5] = part;
            __syncthreads();
            if (tid < 32) {
                float v2 = (tid < NT/32) ? red[tid] : 0.f;
                #pragma unroll
                for (int o = 8; o; o >>= 1) v2 += __shfl_down_sync(0xffffffffu, v2, o);
                if (tid == 0) atomicAdd(&out[step - RELAX], v2 * s_pminv);
            }
        }

        // ---- wait: EVERY CTA polls the monotonic counter directly ----
        if (tid == 0) {
            const unsigned need = (unsigned)(step + 1) * (unsigned)NCTA;
            unsigned v;
            do {
                asm volatile("ld.acquire.gpu.u32 %0, [%1];" : "=r"(v) : "l"(&g_count) : "memory");
            } while (v < need);
        }
        __syncthreads();
    }
}

// ---------------- host launcher: ONE graph node ----------------
extern "C" void kernel_launch(void* const* d_in, const int* in_sizes, int n_in,
                              void* d_out, int out_size)
{
    const float* sig   = (const float*)d_in[0];
    const float* Bext  = (const float*)d_in[1];
    const float* Msat  = (const float*)d_in[2];
    const float* src   = (const float*)d_in[3];
    const float* pmask = (const float*)d_in[4];
    float* out = (float*)d_out;

    dim3 grid(NBX, NBY);
    k_sim<<<grid, NT>>>(sig, Bext, Msat, src, pmask, out);
}

// round 10
// speedup vs baseline: 1.5596x; 1.0647x over previous
#include <cuda_runtime.h>

// ---------------- problem constants ----------------
#define NXg 256
#define NYg 256
#define NG  (NXg*NYg)

// tile: interior 16(x) x 32(y), halo 4 -> ext 24x40; strips of 2 in y
#define IXt 16
#define IYt 32
#define Hh  4
#define EXt 24
#define EYt 40
#define EXT (EXt*EYt)      // 960
#define SW   2
#define NSTR (EYt/SW)      // 20
#define NSTRIPS (EXt*NSTR) // 480
#define NT   512
#define NBX (NYg/IYt)      // 8
#define NBY (NXg/IXt)      // 16
#define NCTA (NBX*NBY)     // 128 CTAs <= 148 SMs -> co-resident
#define RELAX  100
#define TSTEPS 1024
#define NSTEPS (RELAX + TSTEPS)

// ---------------- device state ----------------
__device__ float g_m[2][3*NG];   // ping-pong exchange state
__device__ unsigned g_count;     // MONOTONIC arrival counter (reset at kernel start)
__device__ unsigned g_ibar;      // init barrier counter (self-resetting)
__device__ unsigned g_isense;    // init barrier sense (2 flips/run -> replay-safe)

// init-only sense-reversing barrier (used exactly twice per run)
__device__ __forceinline__ void initbar(unsigned& lsense)
{
    __syncthreads();
    if (threadIdx.x == 0) {
        unsigned s = lsense ^ 1u;
        lsense = s;
        unsigned old;
        asm volatile("atom.add.acq_rel.gpu.u32 %0, [%1], 1;"
                     : "=r"(old) : "l"(&g_ibar) : "memory");
        if (old == NCTA - 1u) {
            asm volatile("st.relaxed.gpu.u32 [%0], %1;" :: "l"(&g_ibar), "r"(0u) : "memory");
            asm volatile("st.release.gpu.u32 [%0], %1;" :: "l"(&g_isense), "r"(s) : "memory");
        } else {
            unsigned v;
            do {
                asm volatile("ld.acquire.gpu.u32 %0, [%1];" : "=r"(v) : "l"(&g_isense) : "memory");
            } while (v != s);
        }
    }
    __syncthreads();
}

// max RK substage (1..4) at which a strip must still be computed; -1 = dead.
// Per-cell rule identical to the validated R2 smax: a side only shrinks the
// valid region if that ext edge is interior to the domain.
__device__ __forceinline__ int strip_cap(int ex, int sy, int gx0, int gy0)
{
    int gx = gx0 + ex;
    int cap = -1;
    #pragma unroll
    for (int j = 0; j < SW; j++) {
        int ey = SW*sy + j;
        int gy = gy0 + ey;
        if (gx < 0 || gx >= NXg || gy < 0 || gy >= NYg) continue;
        int c = 99;
        if (gx0 >= 0)         c = min(c, ex);
        if (gx0 + EXt <= NXg) c = min(c, EXt - 1 - ex);
        if (gy0 >= 0)         c = min(c, ey);
        if (gy0 + EYt <= NYg) c = min(c, EYt - 1 - ey);
        cap = max(cap, min(c, 4));
    }
    return cap;
}

__global__ void __launch_bounds__(NT, 1)
k_sim(const float* __restrict__ sig,  const float* __restrict__ Bext,
      const float* __restrict__ Msat, const float* __restrict__ src,
      const float* __restrict__ pmask, float* __restrict__ out)
{
    __shared__ __align__(16) float SA[3][EXT];
    __shared__ __align__(16) float SB[3][EXT];
    __shared__ float red[NT/32];
    __shared__ float s_pminv;
    __shared__ float s_sig[TSTEPS];
    __shared__ signed char sClass[NSTRIPS];
    __shared__ short sOwner[NSTRIPS];

    const int tid = threadIdx.x;
    const int gx0 = (int)blockIdx.y * IXt - Hh;
    const int gy0 = (int)blockIdx.x * IYt - Hh;
    const bool cta0 = (blockIdx.x == 0 && blockIdx.y == 0);

    // ---- deterministic cap-ordered thread->strip mapping ----
    if (tid < NSTRIPS) {
        sClass[tid] = (signed char)strip_cap(tid / NSTR, tid % NSTR, gx0, gy0);
        sOwner[tid] = -1;
    }
    __syncthreads();
    if (tid < NSTRIPS && sClass[tid] >= 0) {
        int myc = sClass[tid];
        int r = 0;
        for (int s = 0; s < NSTRIPS; ++s) {
            int cs = sClass[s];
            r += (cs > myc) || (cs == myc && s < tid);
        }
        sOwner[r] = (short)tid;
    }
    __syncthreads();
    const int myStrip = (tid < NSTRIPS) ? (int)sOwner[tid] : -1;
    const bool live = (myStrip >= 0);
    const int ex  = live ? myStrip / NSTR : 0;
    const int sy  = live ? myStrip % NSTR : 0;
    const int scap = live ? strip_cap(ex, sy, gx0, gy0) : -1;

    const int gx  = gx0 + ex;
    const int gyb = gy0 + SW*sy;
    const int e   = ex*EYt + SW*sy;

    const int gxc = min(max(gx, 0), NXg - 1);
    const int gyc = min(max(gyb, 0), NYg - SW);
    const int g   = gxc*NYg + gyc;

    const int exm = (ex == 0       || gx <= 0)       ? ex : ex - 1;
    const int exq = (ex == EXt - 1 || gx >= NXg - 1) ? ex : ex + 1;
    const int emb = exm*EYt + SW*sy;
    const int epb = exq*EYt + SW*sy;
    const int yL = (sy == 0        || gyb <= 0)                ? e          : e - 1;
    const int yR = (sy == NSTR - 1 || gyb + SW - 1 >= NYg - 1) ? e + SW - 1 : e + SW;

    const bool sint = (scap >= 4);   // interior <=> needed through stage 4
    const bool ring = sint && (ex < Hh + 4 || ex >= Hh + IXt - 4 ||
                               sy < Hh/SW + 2 || sy >= (Hh + IYt)/SW - 2);

    const float MU0f    = (float)(4e-7 * 3.14159265358979323846);
    const float TWO_A   = (float)(2.0 * 3.65e-12);
    const float INV_DX2 = (float)(1.0 / (50e-9 * 50e-9));
    const double hd  = 1.7595e11 * 5e-12;
    const float c05  = (float)(0.5 * hd);
    const float cfl  = (float)hd;
    const float h6   = (float)(hd / 6.0);
    const float i_rx = (float)(1.0 / (1.0 + 0.5 * 0.5));
    const float i_rn = (float)(1.0 / (1.0 + 0.01 * 0.01));
    // folded (negative) coefficients: st = fma(nC, k', mb), k' = p + alpha*q
    const float nC05_rx = -(c05 * i_rx), nCfl_rx = -(cfl * i_rx), nH6_rx = -(h6 * i_rx);
    const float nC05_rn = -(c05 * i_rn), nCfl_rn = -(cfl * i_rn), nH6_rn = -(h6 * i_rn);

    // -------- static per-cell constants (registers, whole run) --------
    float rB0[SW], rB1[SW], rB2[SW], rS0[SW], rS1[SW], rS2[SW];
    float rCL[SW], rDg[SW], pmw[SW], m0x[SW];
    int anyp = 0;
    #pragma unroll
    for (int j = 0; j < SW; j++) {
        int gj = live ? gx*NYg + (gyb + j) : 0;   // live strips are fully in-domain
        float ms = Msat[gj];
        rCL[j] = (TWO_A / ms) * INV_DX2;
        rDg[j] = MU0f * ms;
        rB0[j] = Bext[0*NG + gj]; rB1[j] = Bext[1*NG + gj]; rB2[j] = Bext[2*NG + gj];
        rS0[j] = src [0*NG + gj]; rS1[j] = src [1*NG + gj]; rS2[j] = src [2*NG + gj];
        float pv = sint ? pmask[gj] : 0.f;
        pmw[j] = pv * ms;
        m0x[j] = 0.f;
        if (pv != 0.f) anyp = 1;
    }

    for (int i = tid; i < TSTEPS; i += NT) s_sig[i] = sig[i];
    if (cta0) {
        for (int i = tid; i < TSTEPS; i += NT) out[i] = 0.f;
        if (tid == 0)
            asm volatile("st.relaxed.gpu.u32 [%0], %1;" :: "l"(&g_count), "r"(0u) : "memory");
    }

    const int hasp = __syncthreads_or(anyp);
    if (hasp) {
        float s = 0.f;
        for (int i = tid; i < NG; i += NT) s += pmask[i];
        #pragma unroll
        for (int o = 16; o; o >>= 1) s += __shfl_down_sync(0xffffffffu, s, o);
        if ((tid & 31) == 0) red[tid >> 5] = s;
        __syncthreads();
        if (tid < 32) {
            float v = (tid < NT/32) ? red[tid] : 0.f;
            #pragma unroll
            for (int o = 8; o; o >>= 1) v += __shfl_down_sync(0xffffffffu, v, o);
            if (tid == 0) s_pminv = 1.f / v;
        }
    }

    unsigned lsense = 0;
    initbar(lsense);
    initbar(lsense);

    float mb0[SW], mb1[SW], mb2[SW];
    #pragma unroll
    for (int j = 0; j < SW; j++) { mb0[j] = 0.f; mb1[j] = 0.f; mb2[j] = 1.f; }
    if (live) {
        *(float2*)&SA[0][e] = make_float2(0.f, 0.f);
        *(float2*)&SA[1][e] = make_float2(0.f, 0.f);
        *(float2*)&SA[2][e] = make_float2(1.f, 1.f);
    }
    __syncthreads();

    for (int step = 0; step < NSTEPS; ++step) {
        const bool  probe = (step >= RELAX);
        const float sv    = probe ? s_sig[step - RELAX] : 0.f;
        const float alpha = probe ? 0.01f : 0.5f;
        const float nC05  = probe ? nC05_rn : nC05_rx;
        const float nCfl  = probe ? nCfl_rn : nCfl_rx;
        const float nH6   = probe ? nH6_rn  : nH6_rx;
        const float* __restrict__ m_in  = g_m[(step + 1) & 1];
        float*       __restrict__ m_out = g_m[step & 1];

        // ---- halo refresh from L2 ----
        if (live && !sint && step > 0) {
            float2 a = __ldcg((const float2*)&m_in[0*NG + g]);
            float2 b = __ldcg((const float2*)&m_in[1*NG + g]);
            float2 c = __ldcg((const float2*)&m_in[2*NG + g]);
            mb0[0]=a.x; mb0[1]=a.y;
            mb1[0]=b.x; mb1[1]=b.y;
            mb2[0]=c.x; mb2[1]=c.y;
            *(float2*)&SA[0][e] = a; *(float2*)&SA[1][e] = b; *(float2*)&SA[2][e] = c;
        }

        float tB0[SW], tB1[SW], tB2[SW];
        float st0[SW], st1[SW], st2[SW];
        float a0[SW], a1[SW], a2[SW];
        #pragma unroll
        for (int j = 0; j < SW; j++) {
            tB0[j] = fmaf(sv, rS0[j], rB0[j]);
            tB1[j] = fmaf(sv, rS1[j], rB1[j]);
            tB2[j] = fmaf(sv, rS2[j], rB2[j]);
            st0[j] = mb0[j]; st1[j] = mb1[j]; st2[j] = mb2[j];
            a0[j] = 0.f; a1[j] = 0.f; a2[j] = 0.f;
        }
        __syncthreads();

        // one RK substage; k' = p + alpha*q (sign & inv1a folded into coefs)
        auto stage = [&](const float (*__restrict__ S)[EXT],
                         float (*__restrict__ D)[EXT],
                         float nCoef, float w, bool writeD) {
            float2 nm0 = *(const float2*)&S[0][emb];
            float2 nm1 = *(const float2*)&S[1][emb];
            float2 nm2 = *(const float2*)&S[2][emb];
            float2 np0 = *(const float2*)&S[0][epb];
            float2 np1 = *(const float2*)&S[1][epb];
            float2 np2 = *(const float2*)&S[2][epb];
            float lf0 = S[0][yL], lf1 = S[1][yL], lf2 = S[2][yL];
            float rg0 = S[0][yR], rg1 = S[1][yR], rg2 = S[2][yR];
            float xm0[SW] = {nm0.x, nm0.y}, xm1[SW] = {nm1.x, nm1.y}, xm2[SW] = {nm2.x, nm2.y};
            float xp0[SW] = {np0.x, np0.y}, xp1[SW] = {np1.x, np1.y}, xp2[SW] = {np2.x, np2.y};
            #pragma unroll
            for (int j = 0; j < SW; j++) {
                float mx = st0[j], my = st1[j], mz = st2[j];
                float yl0 = j ? st0[j-1] : lf0;
                float yl1 = j ? st1[j-1] : lf1;
                float yl2 = j ? st2[j-1] : lf2;
                float yr0 = (j < SW-1) ? st0[j+1] : rg0;
                float yr1 = (j < SW-1) ? st1[j+1] : rg1;
                float yr2 = (j < SW-1) ? st2[j+1] : rg2;
                float l0 = xm0[j] + xp0[j] + yl0 + yr0 - 4.f*mx;
                float l1 = xm1[j] + xp1[j] + yl1 + yr1 - 4.f*my;
                float l2 = xm2[j] + xp2[j] + yl2 + yr2 - 4.f*mz;
                float Bx = fmaf(rCL[j], l0, tB0[j]);
                float By = fmaf(rCL[j], l1, tB1[j]);
                float Bz = fmaf(rCL[j], l2, tB2[j]) - rDg[j]*mz;
                float px = my*Bz - mz*By;
                float py = mz*Bx - mx*Bz;
                float pz = mx*By - my*Bx;
                float qx = my*pz - mz*py;
                float qy = mz*px - mx*pz;
                float qz = mx*py - my*px;
                float k0 = fmaf(alpha, qx, px);   // k' (unscaled)
                float k1 = fmaf(alpha, qy, py);
                float k2 = fmaf(alpha, qz, pz);
                a0[j] = fmaf(w, k0, a0[j]);
                a1[j] = fmaf(w, k1, a1[j]);
                a2[j] = fmaf(w, k2, a2[j]);
                st0[j] = fmaf(nCoef, k0, mb0[j]);
                st1[j] = fmaf(nCoef, k1, mb1[j]);
                st2[j] = fmaf(nCoef, k2, mb2[j]);
            }
            if (writeD) {
                *(float2*)&D[0][e] = make_float2(st0[0], st0[1]);
                *(float2*)&D[1][e] = make_float2(st1[0], st1[1]);
                *(float2*)&D[2][e] = make_float2(st2[0], st2[1]);
            }
        };

        // stage s only for strips needed at stage s (warp-aligned by mapping)
        if (scap >= 1) stage(SA, SB, nC05, 1.f, true);
        __syncthreads();
        if (scap >= 2) stage(SB, SA, nC05, 2.f, true);
        __syncthreads();
        if (scap >= 3) stage(SA, SB, nCfl, 2.f, true);
        __syncthreads();
        if (scap >= 4) stage(SB, SA, 0.f, 1.f, false);   // k4 folded into acc

        // ---- final m (interior): SA publish + exchange ring to L2 ----
        float part = 0.f;
        if (sint) {
            #pragma unroll
            for (int j = 0; j < SW; j++) {
                mb0[j] = fmaf(nH6, a0[j], mb0[j]);
                mb1[j] = fmaf(nH6, a1[j], mb1[j]);
                mb2[j] = fmaf(nH6, a2[j], mb2[j]);
                if (step == RELAX - 1) m0x[j] = mb0[j];
                if (probe) part += (mb0[j] - m0x[j]) * pmw[j];
            }
            float2 a = make_float2(mb0[0], mb0[1]);
            float2 b = make_float2(mb1[0], mb1[1]);
            float2 c = make_float2(mb2[0], mb2[1]);
            *(float2*)&SA[0][e] = a; *(float2*)&SA[1][e] = b; *(float2*)&SA[2][e] = c;
            if (ring) {
                __stcg((float2*)&m_out[0*NG + g], a);
                __stcg((float2*)&m_out[1*NG + g], b);
                __stcg((float2*)&m_out[2*NG + g], c);
            }
        }

        if (step == NSTEPS - 1) {
            if (probe && hasp) {
                #pragma unroll
                for (int o = 16; o; o >>= 1) part += __shfl_down_sync(0xffffffffu, part, o);
                if ((tid & 31) == 0) red[tid >> 5] = part;
                __syncthreads();
                if (tid < 32) {
                    float v2 = (tid < NT/32) ? red[tid] : 0.f;
                    #pragma unroll
                    for (int o = 8; o; o >>= 1) v2 += __shfl_down_sync(0xffffffffu, v2, o);
                    if (tid == 0) atomicAdd(&out[step - RELAX], v2 * s_pminv);
                }
            }
            break;
        }

        // ---- arrive: fire-and-forget, orders prior ring stores ----
        __syncthreads();
        if (tid == 0)
            asm volatile("red.add.release.gpu.u32 [%0], %1;"
                         :: "l"(&g_count), "r"(1u) : "memory");

        // ---- probe reduction overlaps other CTAs' spin ----
        if (probe && hasp) {
            #pragma unroll
            for (int o = 16; o; o >>= 1) part += __shfl_down_sync(0xffffffffu, part, o);
            if ((tid & 31) == 0) red[tid >> 5] = part;
            __syncthreads();
            if (tid < 32) {
                float v2 = (tid < NT/32) ? red[tid] : 0.f;
                #pragma unroll
                for (int o = 8; o; o >>= 1) v2 += __shfl_down_sync(0xffffffffu, v2, o);
                if (tid == 0) atomicAdd(&out[step - RELAX], v2 * s_pminv);
            }
        }

        // ---- wait: every CTA polls the monotonic counter directly ----
        if (tid == 0) {
            const unsigned need = (unsigned)(step + 1) * (unsigned)NCTA;
            unsigned v;
            do {
                asm volatile("ld.acquire.gpu.u32 %0, [%1];" : "=r"(v) : "l"(&g_count) : "memory");
            } while (v < need);
        }
        __syncthreads();
    }
}

// ---------------- host launcher: ONE graph node ----------------
extern "C" void kernel_launch(void* const* d_in, const int* in_sizes, int n_in,
                              void* d_out, int out_size)
{
    const float* sig   = (const float*)d_in[0];
    const float* Bext  = (const float*)d_in[1];
    const float* Msat  = (const float*)d_in[2];
    const float* src   = (const float*)d_in[3];
    const float* pmask = (const float*)d_in[4];
    float* out = (float*)d_out;

    dim3 grid(NBX, NBY);
    k_sim<<<grid, NT>>>(sig, Bext, Msat, src, pmask, out);
}